// round 1
// baseline (speedup 1.0000x reference)
#include <cuda_runtime.h>

#define NMAX 100000
#define HD 128
#define BO_PAD 258   // padded k-major B row (256 cols + 2) -> aligned float2, reduced bank conflicts

// Scratch (allocation-free rule: static __device__ arrays)
__device__ float g_z [NMAX * HD];
__device__ float g_zi[NMAX * HD];
__device__ float g_ss[NMAX];
__device__ float g_sd[NMAX];
__device__ float g_h1[NMAX * HD];

// ---- packed f32x2 helpers (2x fp32 FMA throughput on sm_103a) ----
__device__ __forceinline__ double dup2(float x) {
    double d; asm("mov.b64 %0, {%1, %1};" : "=d"(d) : "f"(x)); return d;
}
__device__ __forceinline__ double fma2(double a, double b, double c) {
    asm("fma.rn.f32x2 %0, %1, %2, %0;" : "+d"(c) : "d"(a), "d"(b)); return c;
}
__device__ __forceinline__ float2 unpack2(double d) {
    float2 u; asm("mov.b64 {%0, %1}, %2;" : "=f"(u.x), "=f"(u.y) : "d"(d)); return u;
}

// Fused GEMM: Z = A @ Ww^T, Zi = A @ Wu^T, plus epilogue row-dots
// Ssrc = Z @ a_src, Sdst = Z @ a_dst  (a_src = Wa[0:128], a_dst = Wa[128:256]).
// Tile: BM=128 rows x BO=256 cols (cols 0..127 -> Z, 128..255 -> Zi), full K=128.
// 512 threads; thread (warp w, lane l) owns rows w*8..w*8+7, col-pairs 2l+64j (j=0..3).
__global__ __launch_bounds__(512, 1)
void gemm_fused(const float* __restrict__ A, const float* __restrict__ Ww,
                const float* __restrict__ Wu, const float* __restrict__ Wa,
                float* __restrict__ Z, float* __restrict__ Zi,
                float* __restrict__ Ssrc, float* __restrict__ Sdst, int n)
{
    extern __shared__ float sm[];
    float* As  = sm;               // [128][128] row-major
    float* Bst = sm + 128 * HD;    // [128][BO_PAD] k-major (transposed weights)

    const int tid  = threadIdx.x;
    const int row0 = blockIdx.x * 128;

    // Load A tile (zero-pad past n)
    for (int i = tid; i < 128 * (HD / 4); i += 512) {
        int r = i >> 5, c4 = i & 31;
        float4 v = make_float4(0.f, 0.f, 0.f, 0.f);
        if (row0 + r < n) v = *(const float4*)(A + (size_t)(row0 + r) * HD + c4 * 4);
        *(float4*)(As + r * HD + c4 * 4) = v;
    }
    // Load W_W (cols 0..127) + W_U (cols 128..255), transposed to k-major
    for (int i = tid; i < 256 * (HD / 4); i += 512) {
        int o = i >> 5, k4 = i & 31;
        const float* W = (o < 128) ? Ww : Wu;
        int oo = o & 127;
        float4 v = *(const float4*)(W + oo * HD + k4 * 4);
        Bst[(k4 * 4 + 0) * BO_PAD + o] = v.x;
        Bst[(k4 * 4 + 1) * BO_PAD + o] = v.y;
        Bst[(k4 * 4 + 2) * BO_PAD + o] = v.z;
        Bst[(k4 * 4 + 3) * BO_PAD + o] = v.w;
    }
    __syncthreads();

    const int warp = tid >> 5, lane = tid & 31;

    double acc[8][4];
    #pragma unroll
    for (int r = 0; r < 8; r++)
        #pragma unroll
        for (int j = 0; j < 4; j++) acc[r][j] = 0.0;

    const float* arow  = As + (warp * 8) * HD;
    const float* bbase = Bst + 2 * lane;

    #pragma unroll 4
    for (int k = 0; k < HD; k++) {
        double b0 = *(const double*)(bbase + k * BO_PAD);
        double b1 = *(const double*)(bbase + k * BO_PAD + 64);
        double b2 = *(const double*)(bbase + k * BO_PAD + 128);
        double b3 = *(const double*)(bbase + k * BO_PAD + 192);
        #pragma unroll
        for (int r = 0; r < 8; r++) {
            double a = dup2(arow[r * HD + k]);   // broadcast LDS (conflict-free)
            acc[r][0] = fma2(a, b0, acc[r][0]);
            acc[r][1] = fma2(a, b1, acc[r][1]);
            acc[r][2] = fma2(a, b2, acc[r][2]);
            acc[r][3] = fma2(a, b3, acc[r][3]);
        }
    }

    // Epilogue: store Z/Zi, fused s_src/s_dst row-dots (warp owns a full Z row)
    float as_[2][2], ad_[2][2];
    #pragma unroll
    for (int j = 0; j < 2; j++) {
        int c = 2 * lane + 64 * j;
        as_[j][0] = Wa[c];       as_[j][1] = Wa[c + 1];
        ad_[j][0] = Wa[128 + c]; ad_[j][1] = Wa[128 + c + 1];
    }
    #pragma unroll
    for (int r = 0; r < 8; r++) {
        int row = row0 + warp * 8 + r;
        bool ok = row < n;
        float ss = 0.f, sd = 0.f;
        #pragma unroll
        for (int j = 0; j < 2; j++) {          // Z cols
            float2 v = unpack2(acc[r][j]);
            ss += v.x * as_[j][0] + v.y * as_[j][1];
            sd += v.x * ad_[j][0] + v.y * ad_[j][1];
            if (ok) *(float2*)(Z + (size_t)row * HD + 2 * lane + 64 * j) = v;
        }
        #pragma unroll
        for (int j = 2; j < 4; j++) {          // Zi cols
            float2 v = unpack2(acc[r][j]);
            if (ok) *(float2*)(Zi + (size_t)row * HD + 2 * lane + 64 * (j - 2)) = v;
        }
        #pragma unroll
        for (int off = 16; off; off >>= 1) {
            ss += __shfl_xor_sync(0xffffffffu, ss, off);
            sd += __shfl_xor_sync(0xffffffffu, sd, off);
        }
        if (ok && lane == 0) { Ssrc[row] = ss; Sdst[row] = sd; }
    }
}

// Edge kernel: one warp per node. edge_dst = repeat(arange(n),16) => node i owns
// edges [16i, 16i+16): segment softmax is a warp-local shuffle reduction.
// Lanes 16..31 mirror lanes 0..15 for the scalar phase; all 32 lanes cooperate
// on the 128-dim weighted gather-sum (float4 per lane).
__global__ __launch_bounds__(256)
void edge_kernel(const float* __restrict__ Z, const float* __restrict__ Zi,
                 const float* __restrict__ Ssrc, const float* __restrict__ Sdst,
                 const float* __restrict__ edge_d, const int* __restrict__ esrc,
                 const float* __restrict__ W_V, const float* __restrict__ Wa,
                 float* __restrict__ out, int n)
{
    int gw = (blockIdx.x * blockDim.x + threadIdx.x) >> 5;
    if (gw >= n) return;
    const int lane = threadIdx.x & 31;
    const int node = gw;
    const float cva = W_V[0] * Wa[2 * HD];   // t @ a_t = edge_d * (W_V * a_t)

    int   e   = node * 16 + (lane & 15);
    int   src = esrc[e];
    float ee  = Ssrc[src] + Sdst[node] + edge_d[e] * cva;
    ee = ee > 0.f ? ee : 0.01f * ee;         // leaky relu

    float m = ee;
    #pragma unroll
    for (int off = 8; off; off >>= 1) m = fmaxf(m, __shfl_xor_sync(0xffffffffu, m, off));
    float ex = __expf(ee - m);
    float s = ex;
    #pragma unroll
    for (int off = 8; off; off >>= 1) s += __shfl_xor_sync(0xffffffffu, s, off);
    float alpha = ex / s;

    float4 acc = make_float4(0.f, 0.f, 0.f, 0.f);
    #pragma unroll
    for (int j = 0; j < 16; j++) {           // 16 independent LDG.128 -> high MLP
        float aj = __shfl_sync(0xffffffffu, alpha, j);
        int   sj = __shfl_sync(0xffffffffu, src,   j);
        float4 v = *(const float4*)(Z + (size_t)sj * HD + lane * 4);
        acc.x += aj * v.x; acc.y += aj * v.y; acc.z += aj * v.z; acc.w += aj * v.w;
    }

    float4 zv = *(const float4*)(Zi + (size_t)node * HD + lane * 4);
    float4 o;
    o.x = fmaxf(zv.x + acc.x, 0.f);
    o.y = fmaxf(zv.y + acc.y, 0.f);
    o.z = fmaxf(zv.z + acc.z, 0.f);
    o.w = fmaxf(zv.w + acc.w, 0.f);
    *(float4*)(out + (size_t)node * HD + lane * 4) = o;
}

extern "C" void kernel_launch(void* const* d_in, const int* in_sizes, int n_in,
                              void* d_out, int out_size)
{
    const float* attr   = (const float*)d_in[0];
    const float* edge_d = (const float*)d_in[1];
    const float* W_V1   = (const float*)d_in[2];
    const float* W_W1   = (const float*)d_in[3];
    const float* W_U1   = (const float*)d_in[4];
    const float* W_a1   = (const float*)d_in[5];
    const float* W_V2   = (const float*)d_in[6];
    const float* W_W2   = (const float*)d_in[7];
    const float* W_U2   = (const float*)d_in[8];
    const float* W_a2   = (const float*)d_in[9];
    const int*   esrc   = (const int*)d_in[10];
    // d_in[11] = edge_dst: structural (repeat(arange(n),16)), not needed

    const int n = in_sizes[0] / HD;

    float *zp, *zip, *ssp, *sdp, *h1p;
    cudaGetSymbolAddress((void**)&zp,  g_z);
    cudaGetSymbolAddress((void**)&zip, g_zi);
    cudaGetSymbolAddress((void**)&ssp, g_ss);
    cudaGetSymbolAddress((void**)&sdp, g_sd);
    cudaGetSymbolAddress((void**)&h1p, g_h1);

    const int smem = (128 * HD + HD * BO_PAD) * (int)sizeof(float);  // ~193 KB
    cudaFuncSetAttribute(gemm_fused, cudaFuncAttributeMaxDynamicSharedMemorySize, smem);

    const int gb = (n + 127) / 128;
    const int eb = (n + 7) / 8;

    // Layer 1
    gemm_fused<<<gb, 512, smem>>>(attr, W_W1, W_U1, W_a1, zp, zip, ssp, sdp, n);
    edge_kernel<<<eb, 256>>>(zp, zip, ssp, sdp, edge_d, esrc, W_V1, W_a1, h1p, n);
    // Layer 2
    gemm_fused<<<gb, 512, smem>>>(h1p, W_W2, W_U2, W_a2, zp, zip, ssp, sdp, n);
    edge_kernel<<<eb, 256>>>(zp, zip, ssp, sdp, edge_d, esrc, W_V2, W_a2, (float*)d_out, n);
}

// round 3
// speedup vs baseline: 1.6346x; 1.6346x over previous
#include <cuda_runtime.h>
#include <cuda_bf16.h>
#include <cstdint>

#define NMAX 100000
#define HD 128

// Scratch (allocation-free rule)
__device__ float g_z [NMAX * HD];
__device__ float g_zi[NMAX * HD];
__device__ float g_ss[NMAX];
__device__ float g_sd[NMAX];
__device__ float g_h1[NMAX * HD];

// ======================= helpers =======================
__device__ __forceinline__ uint32_t smem_u32(const void* p) {
    uint32_t a;
    asm("{ .reg .u64 t; cvta.to.shared.u64 t, %1; cvt.u32.u64 %0, t; }" : "=r"(a) : "l"(p));
    return a;
}
__device__ __forceinline__ void ldsm4(uint32_t* r, uint32_t addr) {
    asm volatile("ldmatrix.sync.aligned.m8n8.x4.shared.b16 {%0,%1,%2,%3}, [%4];"
                 : "=r"(r[0]), "=r"(r[1]), "=r"(r[2]), "=r"(r[3]) : "r"(addr));
}
__device__ __forceinline__ void mma16816(float* d, const uint32_t* a, const uint32_t* b) {
    asm volatile(
        "mma.sync.aligned.m16n8k16.row.col.f32.bf16.bf16.f32 "
        "{%0,%1,%2,%3}, {%4,%5,%6,%7}, {%8,%9}, {%0,%1,%2,%3};"
        : "+f"(d[0]), "+f"(d[1]), "+f"(d[2]), "+f"(d[3])
        : "r"(a[0]), "r"(a[1]), "r"(a[2]), "r"(a[3]), "r"(b[0]), "r"(b[1]));
}
__device__ __forceinline__ uint32_t packbf2(float x, float y) {
    __nv_bfloat162 h;
    h.x = __float2bfloat16_rn(x); h.y = __float2bfloat16_rn(y);
    return *(uint32_t*)&h;
}

// SMEM byte offsets (all relative to dynamic smem base, 1024-aligned)
#define OF_WA   0          // 256 floats = 1024 B
#define OF_RED  1024       // ssred[128][2] + sdred[128][2] = 2048 B
#define OF_AHI  4096       // 128x128 bf16 = 32768 (row pitch 256B = 16 chunks of 16B, XOR-swizzled)
#define OF_ALO  36864
#define OF_BHI  69632      // 256x128 bf16 = 65536
#define OF_BLO  135168
#define OF_STG  69632      // reuse B after MMA: 128x256 floats = 131072 B (pitch 256 words, XOR-swizzled)
#define SMEM_SZ 200704

// ============ split-bf16 mma.sync GEMM ============
// C[128x256] = A[128x128] @ [Ww;Wu]^T  via D = Ah*Bh + Ah*Bl + Al*Bh (fp32 accum)
// 512 threads = 16 warps as 4x4; warp tile 32 rows x 64 cols.
// Fused epilogue: Z (cols 0..127), Zi (cols 128..255), s_src/s_dst row-dots.
__global__ __launch_bounds__(512, 1)
void gemm_mma(const float* __restrict__ A, const float* __restrict__ Ww,
              const float* __restrict__ Wu, const float* __restrict__ Wa,
              float* __restrict__ Z, float* __restrict__ Zi,
              float* __restrict__ Ssrc, float* __restrict__ Sdst, int n)
{
    extern __shared__ char sm[];
    const uint32_t smb = smem_u32(sm);
    const int tid = threadIdx.x, warp = tid >> 5, lane = tid & 31;
    const int row0 = blockIdx.x * 128;
    const int wr = warp >> 2, wc = warp & 3;        // 4x4 warp grid
    const int r0 = wr * 32, n0 = wc * 64;

    if (tid < 256) ((float*)(sm + OF_WA))[tid] = Wa[tid];

    // ---- convert A tile -> hi/lo bf16, chunk-swizzled (chunk' = chunk ^ (row&7)) ----
    for (int i = tid; i < 2048; i += 512) {         // 128 rows x 16 chunks(16B)
        int r = i >> 4, ch = i & 15;
        float4 v0 = make_float4(0.f,0.f,0.f,0.f), v1 = v0;
        if (row0 + r < n) {
            const float* g = A + (size_t)(row0 + r) * HD + ch * 8;
            v0 = *(const float4*)g; v1 = *(const float4*)(g + 4);
        }
        uint4 hi, lo;
        hi.x = packbf2(v0.x, v0.y); hi.y = packbf2(v0.z, v0.w);
        hi.z = packbf2(v1.x, v1.y); hi.w = packbf2(v1.z, v1.w);
        __nv_bfloat162* hp = (__nv_bfloat162*)&hi;
        lo.x = packbf2(v0.x - __bfloat162float(hp[0].x), v0.y - __bfloat162float(hp[0].y));
        lo.y = packbf2(v0.z - __bfloat162float(hp[1].x), v0.w - __bfloat162float(hp[1].y));
        lo.z = packbf2(v1.x - __bfloat162float(hp[2].x), v1.y - __bfloat162float(hp[2].y));
        lo.w = packbf2(v1.z - __bfloat162float(hp[3].x), v1.w - __bfloat162float(hp[3].y));
        uint32_t off = (uint32_t)r * 256u + (uint32_t)(ch ^ (r & 7)) * 16u;
        *(uint4*)(sm + OF_AHI + off) = hi;
        *(uint4*)(sm + OF_ALO + off) = lo;
    }
    // ---- convert B = [W_W ; W_U] (256 x 128) ----
    for (int i = tid; i < 4096; i += 512) {         // 256 rows x 16 chunks
        int r = i >> 4, ch = i & 15;
        const float* W = (r < 128) ? Ww : Wu;
        const float* g = W + (size_t)(r & 127) * HD + ch * 8;
        float4 v0 = *(const float4*)g, v1 = *(const float4*)(g + 4);
        uint4 hi, lo;
        hi.x = packbf2(v0.x, v0.y); hi.y = packbf2(v0.z, v0.w);
        hi.z = packbf2(v1.x, v1.y); hi.w = packbf2(v1.z, v1.w);
        __nv_bfloat162* hp = (__nv_bfloat162*)&hi;
        lo.x = packbf2(v0.x - __bfloat162float(hp[0].x), v0.y - __bfloat162float(hp[0].y));
        lo.y = packbf2(v0.z - __bfloat162float(hp[1].x), v0.w - __bfloat162float(hp[1].y));
        lo.z = packbf2(v1.x - __bfloat162float(hp[2].x), v1.y - __bfloat162float(hp[2].y));
        lo.w = packbf2(v1.z - __bfloat162float(hp[3].x), v1.w - __bfloat162float(hp[3].y));
        uint32_t off = (uint32_t)r * 256u + (uint32_t)(ch ^ (r & 7)) * 16u;
        *(uint4*)(sm + OF_BHI + off) = hi;
        *(uint4*)(sm + OF_BLO + off) = lo;
    }
    __syncthreads();

    // ---- per-lane ldmatrix row/chunk mapping ----
    // A x4: lanes 0-15 -> rows r0+mi*16+(lane&15), klo; lanes 16-31 -> same rows, khi
    const int arow = (lane & 15);                   // + r0 + mi*16
    const int akb  = lane >> 4;                     // 0/1 within k16 step
    // B x4 (covers 2 n-tiles): row = n0+p*16+((lane>>4)<<3)+(lane&7); kb = (lane>>3)&1
    const int brow = ((lane >> 4) << 3) + (lane & 7);
    const int bkb  = (lane >> 3) & 1;

    float c[2][8][4];
    #pragma unroll
    for (int mi = 0; mi < 2; mi++)
        #pragma unroll
        for (int nt = 0; nt < 8; nt++)
            #pragma unroll
            for (int q = 0; q < 4; q++) c[mi][nt][q] = 0.f;

    #pragma unroll 1
    for (int pass = 0; pass < 3; pass++) {
        const uint32_t abase = smb + ((pass == 2) ? OF_ALO : OF_AHI);
        const uint32_t bbase = smb + ((pass == 1) ? OF_BLO : OF_BHI);
        #pragma unroll
        for (int s = 0; s < 8; s++) {
            uint32_t a[2][4], b[4][4];
            #pragma unroll
            for (int mi = 0; mi < 2; mi++) {
                int r = r0 + mi * 16 + arow;
                uint32_t addr = abase + (uint32_t)r * 256u
                              + (uint32_t)((2 * s + akb) ^ (r & 7)) * 16u;
                ldsm4(a[mi], addr);
            }
            #pragma unroll
            for (int p = 0; p < 4; p++) {
                int r = n0 + p * 16 + brow;
                uint32_t addr = bbase + (uint32_t)r * 256u
                              + (uint32_t)((2 * s + bkb) ^ (r & 7)) * 16u;
                ldsm4(b[p], addr);
            }
            #pragma unroll
            for (int mi = 0; mi < 2; mi++)
                #pragma unroll
                for (int p = 0; p < 4; p++) {
                    mma16816(c[mi][2 * p],     a[mi], &b[p][0]);
                    mma16816(c[mi][2 * p + 1], a[mi], &b[p][2]);
                }
        }
    }
    __syncthreads();   // done reading B; stage buffer reuses it

    // ---- fused s_src/s_dst row-dots (Z cols only: wc<2) ----
    float* red = (float*)(sm + OF_RED);             // [128][2] ss then [128][2] sd
    const float* WaS = (const float*)(sm + OF_WA);
    if (wc < 2) {
        float ssv[2][2] = {{0.f,0.f},{0.f,0.f}}, sdv[2][2] = {{0.f,0.f},{0.f,0.f}};
        #pragma unroll
        for (int mi = 0; mi < 2; mi++)
            #pragma unroll
            for (int nt = 0; nt < 8; nt++) {
                int col = n0 + nt * 8 + (lane & 3) * 2;
                float s0 = WaS[col], s1 = WaS[col + 1];
                float d0 = WaS[128 + col], d1 = WaS[128 + col + 1];
                ssv[mi][0] += c[mi][nt][0] * s0 + c[mi][nt][1] * s1;
                ssv[mi][1] += c[mi][nt][2] * s0 + c[mi][nt][3] * s1;
                sdv[mi][0] += c[mi][nt][0] * d0 + c[mi][nt][1] * d1;
                sdv[mi][1] += c[mi][nt][2] * d0 + c[mi][nt][3] * d1;
            }
        #pragma unroll
        for (int mi = 0; mi < 2; mi++)
            #pragma unroll
            for (int h = 0; h < 2; h++) {
                ssv[mi][h] += __shfl_xor_sync(0xffffffffu, ssv[mi][h], 1);
                ssv[mi][h] += __shfl_xor_sync(0xffffffffu, ssv[mi][h], 2);
                sdv[mi][h] += __shfl_xor_sync(0xffffffffu, sdv[mi][h], 1);
                sdv[mi][h] += __shfl_xor_sync(0xffffffffu, sdv[mi][h], 2);
            }
        if ((lane & 3) == 0) {
            int g = lane >> 2;
            #pragma unroll
            for (int mi = 0; mi < 2; mi++) {
                int rA = r0 + mi * 16 + g;
                red[rA * 2 + wc]             = ssv[mi][0];
                red[(rA + 8) * 2 + wc]       = ssv[mi][1];
                red[256 + rA * 2 + wc]       = sdv[mi][0];
                red[256 + (rA + 8) * 2 + wc] = sdv[mi][1];
            }
        }
    }

    // ---- stage C -> SMEM (XOR-swizzled words), then coalesced global stores ----
    float* stg = (float*)(sm + OF_STG);             // pitch 256 words
    #pragma unroll
    for (int mi = 0; mi < 2; mi++)
        #pragma unroll
        for (int nt = 0; nt < 8; nt++) {
            int col = n0 + nt * 8 + (lane & 3) * 2;
            int rA = r0 + mi * 16 + (lane >> 2), rB = rA + 8;
            int wA = col ^ ((rA & 7) << 3), wB = col ^ ((rB & 7) << 3);
            *(float2*)(stg + rA * 256 + wA) = make_float2(c[mi][nt][0], c[mi][nt][1]);
            *(float2*)(stg + rB * 256 + wB) = make_float2(c[mi][nt][2], c[mi][nt][3]);
        }
    __syncthreads();

    for (int i = tid; i < 8192; i += 512) {         // 128 rows x 64 float4
        int r = i >> 6, w = (i & 63) * 4;
        int grow = row0 + r;
        if (grow < n) {
            float4 v = *(float4*)(stg + r * 256 + (w ^ ((r & 7) << 3)));
            float* dst = (w < 128) ? (Z + (size_t)grow * HD + w)
                                   : (Zi + (size_t)grow * HD + (w - 128));
            *(float4*)dst = v;
        }
    }
    if (tid < 128) {
        int grow = row0 + tid;
        if (grow < n) {
            Ssrc[grow] = red[tid * 2] + red[tid * 2 + 1];
            Sdst[grow] = red[256 + tid * 2] + red[256 + tid * 2 + 1];
        }
    }
}

// ================== edge / attention kernel =====================
__global__ __launch_bounds__(256)
void edge_kernel(const float* __restrict__ Z, const float* __restrict__ Zi,
                 const float* __restrict__ Ssrc, const float* __restrict__ Sdst,
                 const float* __restrict__ edge_d, const int* __restrict__ esrc,
                 const float* __restrict__ W_V, const float* __restrict__ Wa,
                 float* __restrict__ out, int n)
{
    int gw = (blockIdx.x * blockDim.x + threadIdx.x) >> 5;
    if (gw >= n) return;
    const int lane = threadIdx.x & 31;
    const int node = gw;
    const float cva = W_V[0] * Wa[2 * HD];

    int   e   = node * 16 + (lane & 15);
    int   src = esrc[e];
    float ee  = Ssrc[src] + Sdst[node] + edge_d[e] * cva;
    ee = ee > 0.f ? ee : 0.01f * ee;

    float m = ee;
    #pragma unroll
    for (int off = 8; off; off >>= 1) m = fmaxf(m, __shfl_xor_sync(0xffffffffu, m, off));
    float ex = __expf(ee - m);
    float s = ex;
    #pragma unroll
    for (int off = 8; off; off >>= 1) s += __shfl_xor_sync(0xffffffffu, s, off);
    float alpha = ex / s;

    float4 acc = make_float4(0.f, 0.f, 0.f, 0.f);
    #pragma unroll
    for (int j = 0; j < 16; j++) {
        float aj = __shfl_sync(0xffffffffu, alpha, j);
        int   sj = __shfl_sync(0xffffffffu, src,   j);
        float4 v = *(const float4*)(Z + (size_t)sj * HD + lane * 4);
        acc.x += aj * v.x; acc.y += aj * v.y; acc.z += aj * v.z; acc.w += aj * v.w;
    }

    float4 zv = *(const float4*)(Zi + (size_t)node * HD + lane * 4);
    float4 o;
    o.x = fmaxf(zv.x + acc.x, 0.f);
    o.y = fmaxf(zv.y + acc.y, 0.f);
    o.z = fmaxf(zv.z + acc.z, 0.f);
    o.w = fmaxf(zv.w + acc.w, 0.f);
    *(float4*)(out + (size_t)node * HD + lane * 4) = o;
}

extern "C" void kernel_launch(void* const* d_in, const int* in_sizes, int n_in,
                              void* d_out, int out_size)
{
    const float* attr   = (const float*)d_in[0];
    const float* edge_d = (const float*)d_in[1];
    const float* W_V1   = (const float*)d_in[2];
    const float* W_W1   = (const float*)d_in[3];
    const float* W_U1   = (const float*)d_in[4];
    const float* W_a1   = (const float*)d_in[5];
    const float* W_V2   = (const float*)d_in[6];
    const float* W_W2   = (const float*)d_in[7];
    const float* W_U2   = (const float*)d_in[8];
    const float* W_a2   = (const float*)d_in[9];
    const int*   esrc   = (const int*)d_in[10];

    const int n = in_sizes[0] / HD;

    float *zp, *zip, *ssp, *sdp, *h1p;
    cudaGetSymbolAddress((void**)&zp,  g_z);
    cudaGetSymbolAddress((void**)&zip, g_zi);
    cudaGetSymbolAddress((void**)&ssp, g_ss);
    cudaGetSymbolAddress((void**)&sdp, g_sd);
    cudaGetSymbolAddress((void**)&h1p, g_h1);

    cudaFuncSetAttribute(gemm_mma, cudaFuncAttributeMaxDynamicSharedMemorySize, SMEM_SZ);

    const int gb = (n + 127) / 128;
    const int eb = (n + 7) / 8;

    gemm_mma<<<gb, 512, SMEM_SZ>>>(attr, W_W1, W_U1, W_a1, zp, zip, ssp, sdp, n);
    edge_kernel<<<eb, 256>>>(zp, zip, ssp, sdp, edge_d, esrc, W_V1, W_a1, h1p, n);
    gemm_mma<<<gb, 512, SMEM_SZ>>>(h1p, W_W2, W_U2, W_a2, zp, zip, ssp, sdp, n);
    edge_kernel<<<eb, 256>>>(zp, zip, ssp, sdp, edge_d, esrc, W_V2, W_a2, (float*)d_out, n);
}

// round 4
// speedup vs baseline: 2.1289x; 1.3024x over previous
#include <cuda_runtime.h>
#include <cuda_bf16.h>
#include <cuda_fp16.h>
#include <cstdint>

#define NMAX 100000
#define HD 128

// Scratch (allocation-free rule)
__device__ float g_z [NMAX * HD];   // used as __half[ ] (Z in fp16)
__device__ float g_zi[NMAX * HD];
__device__ float g_ss[NMAX];
__device__ float g_sd[NMAX];
__device__ float g_h1[NMAX * HD];

// ======================= helpers =======================
__device__ __forceinline__ uint32_t smem_u32(const void* p) {
    uint32_t a;
    asm("{ .reg .u64 t; cvta.to.shared.u64 t, %1; cvt.u32.u64 %0, t; }" : "=r"(a) : "l"(p));
    return a;
}
__device__ __forceinline__ void ldsm4(uint32_t* r, uint32_t addr) {
    asm volatile("ldmatrix.sync.aligned.m8n8.x4.shared.b16 {%0,%1,%2,%3}, [%4];"
                 : "=r"(r[0]), "=r"(r[1]), "=r"(r[2]), "=r"(r[3]) : "r"(addr));
}
__device__ __forceinline__ void mma16816(float* d, const uint32_t* a, const uint32_t* b) {
    asm volatile(
        "mma.sync.aligned.m16n8k16.row.col.f32.bf16.bf16.f32 "
        "{%0,%1,%2,%3}, {%4,%5,%6,%7}, {%8,%9}, {%0,%1,%2,%3};"
        : "+f"(d[0]), "+f"(d[1]), "+f"(d[2]), "+f"(d[3])
        : "r"(a[0]), "r"(a[1]), "r"(a[2]), "r"(a[3]), "r"(b[0]), "r"(b[1]));
}
__device__ __forceinline__ uint32_t packbf2(float x, float y) {
    __nv_bfloat162 h;
    h.x = __float2bfloat16_rn(x); h.y = __float2bfloat16_rn(y);
    return *(uint32_t*)&h;
}
__device__ __forceinline__ void split8(const float4& v0, const float4& v1, uint4& hi, uint4& lo) {
    hi.x = packbf2(v0.x, v0.y); hi.y = packbf2(v0.z, v0.w);
    hi.z = packbf2(v1.x, v1.y); hi.w = packbf2(v1.z, v1.w);
    __nv_bfloat162* hp = (__nv_bfloat162*)&hi;
    lo.x = packbf2(v0.x - __bfloat162float(hp[0].x), v0.y - __bfloat162float(hp[0].y));
    lo.y = packbf2(v0.z - __bfloat162float(hp[1].x), v0.w - __bfloat162float(hp[1].y));
    lo.z = packbf2(v1.x - __bfloat162float(hp[2].x), v1.y - __bfloat162float(hp[2].y));
    lo.w = packbf2(v1.z - __bfloat162float(hp[3].x), v1.w - __bfloat162float(hp[3].y));
}

// SMEM byte offsets
#define OF_WA   0          // 256 floats
#define OF_RED  1024       // 2KB reduction buffer
#define OF_AHI  4096       // 128x128 bf16 = 32768
#define OF_ALO  36864
#define OF_BHI  69632      // 256x128 bf16 = 65536
#define OF_BLO  135168
#define SMEM_SZ 200704

// ============ persistent split-bf16 mma.sync GEMM ============
// B ([Ww;Wu], 256x128) converted ONCE per CTA; tiles of A streamed with
// register prefetch. Z stored fp16, Zi fp32. Fused s_src/s_dst row-dots.
__global__ __launch_bounds__(512, 1)
void gemm_mma(const float* __restrict__ A, const float* __restrict__ Ww,
              const float* __restrict__ Wu, const float* __restrict__ Wa,
              __half* __restrict__ Zh, float* __restrict__ Zi,
              float* __restrict__ Ssrc, float* __restrict__ Sdst,
              int n, int ntiles)
{
    extern __shared__ char sm[];
    const uint32_t smb = smem_u32(sm);
    const int tid = threadIdx.x, warp = tid >> 5, lane = tid & 31;
    const int wr = warp >> 2, wc = warp & 3;
    const int r0 = wr * 32, n0 = wc * 64;

    if (tid < 256) ((float*)(sm + OF_WA))[tid] = Wa[tid];

    // ---- convert B once ----
    for (int i = tid; i < 4096; i += 512) {          // 256 rows x 16 chunks(16B)
        int r = i >> 4, ch = i & 15;
        const float* W = (r < 128) ? Ww : Wu;
        const float* g = W + (size_t)(r & 127) * HD + ch * 8;
        float4 v0 = *(const float4*)g, v1 = *(const float4*)(g + 4);
        uint4 hi, lo; split8(v0, v1, hi, lo);
        uint32_t off = (uint32_t)r * 256u + (uint32_t)(ch ^ (r & 7)) * 16u;
        *(uint4*)(sm + OF_BHI + off) = hi;
        *(uint4*)(sm + OF_BLO + off) = lo;
    }

    // ldmatrix lane mappings
    const int arow = (lane & 15);
    const int akb  = lane >> 4;
    const int brow = ((lane >> 4) << 3) + (lane & 7);
    const int bkb  = (lane >> 3) & 1;

    // per-thread A chunk mapping: 4 chunks, chunk i -> (row, 16B-chunk)
    int crow[4], cch[4];
    #pragma unroll
    for (int i = 0; i < 4; i++) { int idx = tid + i * 512; crow[i] = idx >> 4; cch[i] = idx & 15; }

    // prefetch first tile
    float4 va[4][2];
    {
        int tile = blockIdx.x;
        int p0 = tile * 128;
        #pragma unroll
        for (int i = 0; i < 4; i++) {
            bool p = (tile < ntiles) && (p0 + crow[i] < n);
            const float* g = A + (size_t)(p0 + crow[i]) * HD + cch[i] * 8;
            va[i][0] = p ? *(const float4*)g       : make_float4(0.f,0.f,0.f,0.f);
            va[i][1] = p ? *(const float4*)(g + 4) : make_float4(0.f,0.f,0.f,0.f);
        }
    }
    __syncthreads();   // B ready

    float* red = (float*)(sm + OF_RED);
    const float* WaS = (const float*)(sm + OF_WA);

    for (int tile = blockIdx.x; tile < ntiles; tile += gridDim.x) {
        const int row0 = tile * 128;

        // ---- convert prefetched A -> smem hi/lo ----
        #pragma unroll
        for (int i = 0; i < 4; i++) {
            uint4 hi, lo; split8(va[i][0], va[i][1], hi, lo);
            uint32_t off = (uint32_t)crow[i] * 256u + (uint32_t)(cch[i] ^ (crow[i] & 7)) * 16u;
            *(uint4*)(sm + OF_AHI + off) = hi;
            *(uint4*)(sm + OF_ALO + off) = lo;
        }
        __syncthreads();

        // ---- MMA: 3 passes x 8 K-steps ----
        float c[2][8][4];
        #pragma unroll
        for (int mi = 0; mi < 2; mi++)
            #pragma unroll
            for (int nt = 0; nt < 8; nt++)
                #pragma unroll
                for (int q = 0; q < 4; q++) c[mi][nt][q] = 0.f;

        #pragma unroll 1
        for (int pass = 0; pass < 3; pass++) {
            const uint32_t abase = smb + ((pass == 2) ? OF_ALO : OF_AHI);
            const uint32_t bbase = smb + ((pass == 1) ? OF_BLO : OF_BHI);
            #pragma unroll
            for (int s = 0; s < 8; s++) {
                uint32_t a[2][4], b[4][4];
                #pragma unroll
                for (int mi = 0; mi < 2; mi++) {
                    int r = r0 + mi * 16 + arow;
                    ldsm4(a[mi], abase + (uint32_t)r * 256u
                                 + (uint32_t)((2 * s + akb) ^ (r & 7)) * 16u);
                }
                #pragma unroll
                for (int p = 0; p < 4; p++) {
                    int r = n0 + p * 16 + brow;
                    ldsm4(b[p], bbase + (uint32_t)r * 256u
                                 + (uint32_t)((2 * s + bkb) ^ (r & 7)) * 16u);
                }
                #pragma unroll
                for (int mi = 0; mi < 2; mi++)
                    #pragma unroll
                    for (int p = 0; p < 4; p++) {
                        mma16816(c[mi][2 * p],     a[mi], &b[p][0]);
                        mma16816(c[mi][2 * p + 1], a[mi], &b[p][2]);
                    }
            }
        }

        // ---- prefetch next tile's A (latency hidden under epilogue) ----
        {
            int pt = tile + gridDim.x;
            int p0 = pt * 128;
            #pragma unroll
            for (int i = 0; i < 4; i++) {
                bool p = (pt < ntiles) && (p0 + crow[i] < n);
                const float* g = A + (size_t)(p0 + crow[i]) * HD + cch[i] * 8;
                va[i][0] = p ? *(const float4*)g       : make_float4(0.f,0.f,0.f,0.f);
                va[i][1] = p ? *(const float4*)(g + 4) : make_float4(0.f,0.f,0.f,0.f);
            }
        }

        // ---- epilogue: row-dots + direct global stores ----
        if (wc < 2) {   // Z columns: row-dots + fp16 stores
            float ssv[2][2] = {{0.f,0.f},{0.f,0.f}}, sdv[2][2] = {{0.f,0.f},{0.f,0.f}};
            #pragma unroll
            for (int mi = 0; mi < 2; mi++)
                #pragma unroll
                for (int nt = 0; nt < 8; nt++) {
                    int col = n0 + nt * 8 + (lane & 3) * 2;
                    float s0 = WaS[col], s1 = WaS[col + 1];
                    float d0 = WaS[128 + col], d1 = WaS[128 + col + 1];
                    ssv[mi][0] += c[mi][nt][0] * s0 + c[mi][nt][1] * s1;
                    ssv[mi][1] += c[mi][nt][2] * s0 + c[mi][nt][3] * s1;
                    sdv[mi][0] += c[mi][nt][0] * d0 + c[mi][nt][1] * d1;
                    sdv[mi][1] += c[mi][nt][2] * d0 + c[mi][nt][3] * d1;
                    int rA = row0 + r0 + mi * 16 + (lane >> 2), rB = rA + 8;
                    __half2 hA, hB;
                    hA = __floats2half2_rn(c[mi][nt][0], c[mi][nt][1]);
                    hB = __floats2half2_rn(c[mi][nt][2], c[mi][nt][3]);
                    if (rA < n) *(__half2*)(Zh + (size_t)rA * HD + col) = hA;
                    if (rB < n) *(__half2*)(Zh + (size_t)rB * HD + col) = hB;
                }
            #pragma unroll
            for (int mi = 0; mi < 2; mi++)
                #pragma unroll
                for (int h = 0; h < 2; h++) {
                    ssv[mi][h] += __shfl_xor_sync(0xffffffffu, ssv[mi][h], 1);
                    ssv[mi][h] += __shfl_xor_sync(0xffffffffu, ssv[mi][h], 2);
                    sdv[mi][h] += __shfl_xor_sync(0xffffffffu, sdv[mi][h], 1);
                    sdv[mi][h] += __shfl_xor_sync(0xffffffffu, sdv[mi][h], 2);
                }
            if ((lane & 3) == 0) {
                int g = lane >> 2;
                #pragma unroll
                for (int mi = 0; mi < 2; mi++) {
                    int rl = r0 + mi * 16 + g;
                    red[rl * 2 + wc]             = ssv[mi][0];
                    red[(rl + 8) * 2 + wc]       = ssv[mi][1];
                    red[256 + rl * 2 + wc]       = sdv[mi][0];
                    red[256 + (rl + 8) * 2 + wc] = sdv[mi][1];
                }
            }
        } else {        // Zi columns: fp32 stores
            #pragma unroll
            for (int mi = 0; mi < 2; mi++)
                #pragma unroll
                for (int nt = 0; nt < 8; nt++) {
                    int col = n0 - 128 + nt * 8 + (lane & 3) * 2;
                    int rA = row0 + r0 + mi * 16 + (lane >> 2), rB = rA + 8;
                    if (rA < n) *(float2*)(Zi + (size_t)rA * HD + col)
                                    = make_float2(c[mi][nt][0], c[mi][nt][1]);
                    if (rB < n) *(float2*)(Zi + (size_t)rB * HD + col)
                                    = make_float2(c[mi][nt][2], c[mi][nt][3]);
                }
        }
        __syncthreads();
        if (tid < 128) {
            int grow = row0 + tid;
            if (grow < n) {
                Ssrc[grow] = red[tid * 2] + red[tid * 2 + 1];
                Sdst[grow] = red[256 + tid * 2] + red[256 + tid * 2 + 1];
            }
        }
        // A-smem overwrite for next tile is guarded by the post-convert sync
    }
}

// ================== edge / attention kernel (Z in fp16) =====================
__global__ __launch_bounds__(256)
void edge_kernel(const __half* __restrict__ Zh, const float* __restrict__ Zi,
                 const float* __restrict__ Ssrc, const float* __restrict__ Sdst,
                 const float* __restrict__ edge_d, const int* __restrict__ esrc,
                 const float* __restrict__ W_V, const float* __restrict__ Wa,
                 float* __restrict__ out, int n)
{
    int gw = (blockIdx.x * blockDim.x + threadIdx.x) >> 5;
    if (gw >= n) return;
    const int lane = threadIdx.x & 31;
    const int node = gw;
    const float cva = W_V[0] * Wa[2 * HD];

    int   e   = node * 16 + (lane & 15);
    int   src = esrc[e];
    float ee  = Ssrc[src] + Sdst[node] + edge_d[e] * cva;
    ee = ee > 0.f ? ee : 0.01f * ee;

    float m = ee;
    #pragma unroll
    for (int off = 8; off; off >>= 1) m = fmaxf(m, __shfl_xor_sync(0xffffffffu, m, off));
    float ex = __expf(ee - m);
    float s = ex;
    #pragma unroll
    for (int off = 8; off; off >>= 1) s += __shfl_xor_sync(0xffffffffu, s, off);
    float alpha = ex / s;

    float4 acc = make_float4(0.f, 0.f, 0.f, 0.f);
    #pragma unroll
    for (int j = 0; j < 16; j++) {
        float aj = __shfl_sync(0xffffffffu, alpha, j);
        int   sj = __shfl_sync(0xffffffffu, src,   j);
        uint2 raw = *(const uint2*)(Zh + (size_t)sj * HD + lane * 4);
        float2 f0 = __half22float2(*(__half2*)&raw.x);
        float2 f1 = __half22float2(*(__half2*)&raw.y);
        acc.x += aj * f0.x; acc.y += aj * f0.y; acc.z += aj * f1.x; acc.w += aj * f1.y;
    }

    float4 zv = *(const float4*)(Zi + (size_t)node * HD + lane * 4);
    float4 o;
    o.x = fmaxf(zv.x + acc.x, 0.f);
    o.y = fmaxf(zv.y + acc.y, 0.f);
    o.z = fmaxf(zv.z + acc.z, 0.f);
    o.w = fmaxf(zv.w + acc.w, 0.f);
    *(float4*)(out + (size_t)node * HD + lane * 4) = o;
}

extern "C" void kernel_launch(void* const* d_in, const int* in_sizes, int n_in,
                              void* d_out, int out_size)
{
    const float* attr   = (const float*)d_in[0];
    const float* edge_d = (const float*)d_in[1];
    const float* W_V1   = (const float*)d_in[2];
    const float* W_W1   = (const float*)d_in[3];
    const float* W_U1   = (const float*)d_in[4];
    const float* W_a1   = (const float*)d_in[5];
    const float* W_V2   = (const float*)d_in[6];
    const float* W_W2   = (const float*)d_in[7];
    const float* W_U2   = (const float*)d_in[8];
    const float* W_a2   = (const float*)d_in[9];
    const int*   esrc   = (const int*)d_in[10];

    const int n = in_sizes[0] / HD;

    float *zp, *zip, *ssp, *sdp, *h1p;
    cudaGetSymbolAddress((void**)&zp,  g_z);
    cudaGetSymbolAddress((void**)&zip, g_zi);
    cudaGetSymbolAddress((void**)&ssp, g_ss);
    cudaGetSymbolAddress((void**)&sdp, g_sd);
    cudaGetSymbolAddress((void**)&h1p, g_h1);
    __half* zhp = (__half*)zp;

    cudaFuncSetAttribute(gemm_mma, cudaFuncAttributeMaxDynamicSharedMemorySize, SMEM_SZ);

    int nsm = 148;
    cudaDeviceGetAttribute(&nsm, cudaDevAttrMultiProcessorCount, 0);

    const int ntiles = (n + 127) / 128;
    const int gb = (nsm < ntiles) ? nsm : ntiles;
    const int eb = (n + 7) / 8;

    gemm_mma<<<gb, 512, SMEM_SZ>>>(attr, W_W1, W_U1, W_a1, zhp, zip, ssp, sdp, n, ntiles);
    edge_kernel<<<eb, 256>>>(zhp, zip, ssp, sdp, edge_d, esrc, W_V1, W_a1, h1p, n);
    gemm_mma<<<gb, 512, SMEM_SZ>>>(h1p, W_W2, W_U2, W_a2, zhp, zip, ssp, sdp, n, ntiles);
    edge_kernel<<<eb, 256>>>(zhp, zip, ssp, sdp, edge_d, esrc, W_V2, W_a2, (float*)d_out, n);
}